// round 4
// baseline (speedup 1.0000x reference)
#include <cuda_runtime.h>
#include <cuda_fp16.h>
#include <stdint.h>

#define F    128
#define H1   64
#define H2   32
#define NC   10
#define NPB  7          // nodes per block
#define RV   119        // valid rows = 7*17
#define THREADS 128     // 4 warps

// ---- shared memory byte offsets ----
#define SM_AHI  0            // 128x128 fp16 (32KB), swizzled
#define SM_ALO  32768
#define SM_BHI  65536        // 64x128 fp16 (16KB)
#define SM_BLO  81920
#define SM_HB   0            // Hbuf 128x65 f32 (33280) overlays AHI/ALO after GEMM
#define SM_W2T  98304        // 8KB
#define SM_WCT  106496       // 1280
#define SM_RBUF 107776       // 7*64*4
#define SM_YBUF 109824       // 7*32*4
#define SM_TOTAL 110848

// fp16 tile: row stride 256B, 16 chunks of 16B; swizzle chunk ^= (row&7)
static __device__ __forceinline__ uint32_t sw_off(int row, int chunk) {
    return (uint32_t)row * 256u + (uint32_t)((chunk ^ (row & 7)) << 4);
}

static __device__ __forceinline__ uint32_t smem_u32(const void* p) {
    uint32_t a;
    asm("{ .reg .u64 t; cvta.to.shared.u64 t, %1; cvt.u32.u64 %0, t; }" : "=r"(a) : "l"(p));
    return a;
}

static __device__ __forceinline__ void ldsm_x4(uint32_t* r, uint32_t addr) {
    asm volatile("ldmatrix.sync.aligned.m8n8.x4.shared.b16 {%0,%1,%2,%3}, [%4];"
                 : "=r"(r[0]), "=r"(r[1]), "=r"(r[2]), "=r"(r[3]) : "r"(addr));
}

static __device__ __forceinline__ void mma16816(float* c, const uint32_t* a, const uint32_t* b) {
    asm volatile(
        "mma.sync.aligned.m16n8k16.row.col.f32.f16.f16.f32 "
        "{%0,%1,%2,%3}, {%4,%5,%6,%7}, {%8,%9}, {%0,%1,%2,%3};"
        : "+f"(c[0]), "+f"(c[1]), "+f"(c[2]), "+f"(c[3])
        : "r"(a[0]), "r"(a[1]), "r"(a[2]), "r"(a[3]), "r"(b[0]), "r"(b[1]));
}

static __device__ __forceinline__ void cvt_hilo(float v, __half& h, __half& l) {
    h = __float2half_rn(v);
    l = __float2half_rn(v - __half2float(h));
}
static __device__ __forceinline__ uint2 pack4(__half h0, __half h1, __half h2, __half h3) {
    __half2 a = __halves2half2(h0, h1);
    __half2 b = __halves2half2(h2, h3);
    uint2 r;
    r.x = *(const uint32_t*)&a;
    r.y = *(const uint32_t*)&b;
    return r;
}

__global__ __launch_bounds__(THREADS, 2) void gcn_mma_kernel(
    const float* __restrict__ x,  const float* __restrict__ nb,
    const float* __restrict__ W1, const float* __restrict__ W2,
    const float* __restrict__ Wc, float* __restrict__ out, int n)
{
    extern __shared__ char sm[];
    const uint32_t sb = smem_u32(sm);
    const int tid = threadIdx.x, wid = tid >> 5, lane = tid & 31;

    // ---- B tiles: W1 [64][128] -> fp16 hi/lo, swizzled ----
    const float4* W1v = (const float4*)W1;
    #pragma unroll
    for (int t = 0; t < 16; t++) {
        int gi = tid + t * THREADS;        // gi = j*32 + f4
        int j = gi >> 5, f4 = gi & 31;     // f4: quad (8B = half chunk)
        float4 v = W1v[gi];
        __half h0, h1, h2, h3, l0, l1, l2, l3;
        cvt_hilo(v.x, h0, l0); cvt_hilo(v.y, h1, l1);
        cvt_hilo(v.z, h2, l2); cvt_hilo(v.w, h3, l3);
        uint32_t off = sw_off(j, f4 >> 1) + (uint32_t)(f4 & 1) * 8u;
        *(uint2*)(sm + SM_BHI + off) = pack4(h0, h1, h2, h3);
        *(uint2*)(sm + SM_BLO + off) = pack4(l0, l1, l2, l3);
    }

    // ---- small weights: W2^T [j][m], Wc^T [m][c] ----
    for (int i2 = tid; i2 < H1 * H2; i2 += THREADS) {
        int m = i2 >> 6, j = i2 & 63;
        ((float*)(sm + SM_W2T))[j * H2 + m] = W2[i2];
    }
    for (int i2 = tid; i2 < H2 * NC; i2 += THREADS) {
        int c = i2 >> 5, m = i2 & 31;
        ((float*)(sm + SM_WCT))[m * NC + c] = Wc[i2];
    }

    // ---- A rows: warp w owns rows r = w + 4t; batched loads (MLP=8) ----
    // load -> l2-normalize -> fp16 hi/lo split -> swizzled STS
    {
        const long gbase = (long)blockIdx.x * NPB;
        #pragma unroll 1
        for (int b0 = 0; b0 < 30; b0 += 8) {
            float4 q[8];
            #pragma unroll
            for (int t = 0; t < 8; t++) {
                int r = wid + (b0 + t) * 4;
                q[t] = make_float4(0.f, 0.f, 0.f, 0.f);
                if (r < RV) {
                    int node = r / 17, sub = r - node * 17;
                    long gnode = gbase + node;
                    if (gnode < n) {
                        const float4* src = (sub == 0)
                            ? (const float4*)(x + gnode * (long)F)
                            : (const float4*)(nb + (gnode * 16 + (sub - 1)) * (long)F);
                        q[t] = src[lane];
                    }
                }
            }
            #pragma unroll
            for (int t = 0; t < 8; t++) {
                int r = wid + (b0 + t) * 4;
                if (r < RV) {
                    float4 v = q[t];
                    float ss = v.x * v.x + v.y * v.y + v.z * v.z + v.w * v.w;
                    #pragma unroll
                    for (int o = 16; o > 0; o >>= 1) ss += __shfl_xor_sync(0xffffffffu, ss, o);
                    float inv = 1.f / fmaxf(sqrtf(ss), 1e-12f);
                    __half h0, h1, h2, h3, l0, l1, l2, l3;
                    cvt_hilo(v.x * inv, h0, l0); cvt_hilo(v.y * inv, h1, l1);
                    cvt_hilo(v.z * inv, h2, l2); cvt_hilo(v.w * inv, h3, l3);
                    uint32_t off = sw_off(r, lane >> 1) + (uint32_t)(lane & 1) * 8u;
                    *(uint2*)(sm + SM_AHI + off) = pack4(h0, h1, h2, h3);
                    *(uint2*)(sm + SM_ALO + off) = pack4(l0, l1, l2, l3);
                }
            }
        }
    }

    // ---- zero padding rows 119..127 (9 rows x 16 chunks, hi & lo) ----
    for (int idx = tid; idx < 144; idx += THREADS) {
        int r = RV + idx / 16, ch = idx & 15;
        uint32_t off = sw_off(r, ch);
        *(uint4*)(sm + SM_AHI + off) = make_uint4(0, 0, 0, 0);
        *(uint4*)(sm + SM_ALO + off) = make_uint4(0, 0, 0, 0);
    }
    __syncthreads();

    // ---- GEMM: warp w computes rows 32w..32w+31 x all 64 cols ----
    // D = Ahi*Bhi^T + Ahi*Blo^T + Alo*Bhi^T (fp32 accum)
    float acc[2][8][4];
    #pragma unroll
    for (int m = 0; m < 2; m++)
        #pragma unroll
        for (int ntl = 0; ntl < 8; ntl++)
            acc[m][ntl][0] = acc[m][ntl][1] = acc[m][ntl][2] = acc[m][ntl][3] = 0.f;

    {
        const int arow = 32 * wid + (lane & 15);
        const int asel = lane >> 4;                 // 0: k0-7, 1: k8-15
        const int bn_local = ((lane >> 4) << 3) + (lane & 7);
        const int bsel = (lane >> 3) & 1;

        #pragma unroll
        for (int kc = 0; kc < 8; kc++) {
            uint32_t bhi[16], blo[16];              // [pair p][4 regs]
            #pragma unroll
            for (int p = 0; p < 4; p++) {
                int bn = 16 * p + bn_local;
                uint32_t boff = sw_off(bn, kc * 2 + bsel);
                ldsm_x4(bhi + p * 4, sb + SM_BHI + boff);
                ldsm_x4(blo + p * 4, sb + SM_BLO + boff);
            }
            uint32_t ahi[2][4], alo[2][4];
            #pragma unroll
            for (int m = 0; m < 2; m++) {
                uint32_t aoff = sw_off(arow + 16 * m, kc * 2 + asel);
                ldsm_x4(ahi[m], sb + SM_AHI + aoff);
                ldsm_x4(alo[m], sb + SM_ALO + aoff);
            }
            #pragma unroll
            for (int m = 0; m < 2; m++) {
                #pragma unroll
                for (int ntl = 0; ntl < 8; ntl++) {
                    const uint32_t* bh = bhi + (ntl >> 1) * 4 + (ntl & 1) * 2;
                    const uint32_t* bl = blo + (ntl >> 1) * 4 + (ntl & 1) * 2;
                    mma16816(acc[m][ntl], ahi[m], bh);
                    mma16816(acc[m][ntl], ahi[m], bl);
                    mma16816(acc[m][ntl], alo[m], bh);
                }
            }
        }
    }
    __syncthreads();   // done reading A/B tiles; Hbuf overlays them

    // ---- write C frags to Hbuf[128][65] ----
    float* hb = (float*)(sm + SM_HB);
    {
        #pragma unroll
        for (int m = 0; m < 2; m++) {
            int r0 = 32 * wid + 16 * m + (lane >> 2);
            int c0 = (lane & 3) * 2;
            #pragma unroll
            for (int ntl = 0; ntl < 8; ntl++) {
                int c = ntl * 8 + c0;
                hb[r0 * 65 + c]           = acc[m][ntl][0];
                hb[r0 * 65 + c + 1]       = acc[m][ntl][1];
                hb[(r0 + 8) * 65 + c]     = acc[m][ntl][2];
                hb[(r0 + 8) * 65 + c + 1] = acc[m][ntl][3];
            }
        }
    }
    __syncthreads();

    // ---- per-node epilogue: warp w handles nodes w, w+4 ----
    #pragma unroll 1
    for (int node = wid; node < NPB; node += 4) {
        long gnode = (long)blockIdx.x * NPB + node;
        if (gnode >= n) break;
        int base = node * 17;
        float hx0 = hb[base * 65 + lane], hx1 = hb[base * 65 + 32 + lane];
        float r0 = 0.f, r1 = 0.f;
        #pragma unroll
        for (int k = 0; k < 16; k++) {
            const float* hr = hb + (base + 1 + k) * 65;
            r0 += fmaxf(hx0 + hr[lane], 0.f);
            r1 += fmaxf(hx1 + hr[32 + lane], 0.f);
        }
        float* rb = (float*)(sm + SM_RBUF) + node * 64;
        rb[lane] = r0;
        rb[lane + 32] = r1;
        __syncwarp();
        const float* W2t = (const float*)(sm + SM_W2T);
        float y = 0.f;
        #pragma unroll
        for (int j = 0; j < H1; j++) y += rb[j] * W2t[j * H2 + lane];
        y = fmaxf(y, 0.f);
        float* yb = (float*)(sm + SM_YBUF) + node * 32;
        yb[lane] = y;
        __syncwarp();
        if (lane < NC) {
            const float* Wct = (const float*)(sm + SM_WCT);
            float o = 0.f;
            #pragma unroll
            for (int m2 = 0; m2 < H2; m2++) o += yb[m2] * Wct[m2 * NC + lane];
            out[gnode * NC + lane] = o;
        }
    }
}

extern "C" void kernel_launch(void* const* d_in, const int* in_sizes, int n_in,
                              void* d_out, int out_size)
{
    const float* x  = (const float*)d_in[0];
    const float* nb = (const float*)d_in[1];
    const float* W1 = (const float*)d_in[2];
    const float* W2 = (const float*)d_in[3];
    const float* Wc = (const float*)d_in[4];
    float* out = (float*)d_out;

    int n = in_sizes[0] / F;
    cudaFuncSetAttribute(gcn_mma_kernel,
                         cudaFuncAttributeMaxDynamicSharedMemorySize, SM_TOTAL);
    int grid = (n + NPB - 1) / NPB;
    gcn_mma_kernel<<<grid, THREADS, SM_TOTAL>>>(x, nb, W1, W2, Wc, out, n);
}

// round 5
// speedup vs baseline: 1.4914x; 1.4914x over previous
#include <cuda_runtime.h>
#include <cuda_fp16.h>
#include <stdint.h>

#define F    128
#define H1   64
#define H2   32
#define NC   10
#define NPB  7          // nodes per block
#define RV   119        // valid rows = 7*17
#define THREADS 256     // 8 warps: 4(M) x 2(N)

// ---- shared memory byte offsets ----
#define SM_AHI  0            // 128x128 fp16 (32KB), swizzled
#define SM_ALO  32768
#define SM_BHI  65536        // 64x128 fp16 (16KB)
#define SM_BLO  81920
#define SM_HB   0            // Hbuf 128x65 f32 (33280) overlays AHI/ALO after GEMM
#define SM_W2T  98304        // 8KB
#define SM_WCT  106496       // 1280
#define SM_RBUF 107776       // 8*64*4
#define SM_YBUF 109824       // 8*32*4
#define SM_TOTAL 110848

// fp16 tile: row stride 256B, 16 chunks of 16B; swizzle chunk ^= (row&7)
static __device__ __forceinline__ uint32_t sw_off(int row, int chunk) {
    return (uint32_t)row * 256u + (uint32_t)((chunk ^ (row & 7)) << 4);
}

static __device__ __forceinline__ uint32_t smem_u32(const void* p) {
    uint32_t a;
    asm("{ .reg .u64 t; cvta.to.shared.u64 t, %1; cvt.u32.u64 %0, t; }" : "=r"(a) : "l"(p));
    return a;
}

static __device__ __forceinline__ void ldsm_x4(uint32_t* r, uint32_t addr) {
    asm volatile("ldmatrix.sync.aligned.m8n8.x4.shared.b16 {%0,%1,%2,%3}, [%4];"
                 : "=r"(r[0]), "=r"(r[1]), "=r"(r[2]), "=r"(r[3]) : "r"(addr));
}

static __device__ __forceinline__ void mma16816(float* c, const uint32_t* a, const uint32_t* b) {
    asm volatile(
        "mma.sync.aligned.m16n8k16.row.col.f32.f16.f16.f32 "
        "{%0,%1,%2,%3}, {%4,%5,%6,%7}, {%8,%9}, {%0,%1,%2,%3};"
        : "+f"(c[0]), "+f"(c[1]), "+f"(c[2]), "+f"(c[3])
        : "r"(a[0]), "r"(a[1]), "r"(a[2]), "r"(a[3]), "r"(b[0]), "r"(b[1]));
}

static __device__ __forceinline__ void cvt_hilo(float v, __half& h, __half& l) {
    h = __float2half_rn(v);
    l = __float2half_rn(v - __half2float(h));
}
static __device__ __forceinline__ uint2 pack4(__half h0, __half h1, __half h2, __half h3) {
    __half2 a = __halves2half2(h0, h1);
    __half2 b = __halves2half2(h2, h3);
    uint2 r;
    r.x = *(const uint32_t*)&a;
    r.y = *(const uint32_t*)&b;
    return r;
}

__global__ __launch_bounds__(THREADS, 2) void gcn_mma_kernel(
    const float* __restrict__ x,  const float* __restrict__ nb,
    const float* __restrict__ W1, const float* __restrict__ W2,
    const float* __restrict__ Wc, float* __restrict__ out, int n)
{
    extern __shared__ char sm[];
    const uint32_t sb = smem_u32(sm);
    const int tid = threadIdx.x, wid = tid >> 5, lane = tid & 31;

    // ---- A-row prefetch: warp w owns rows r = w, w+8, ... (front-batched LDG.128) ----
    float4 q[15];
    const int nr = (RV - 1 - wid) / 8 + 1;
    #pragma unroll
    for (int t = 0; t < 15; t++) {
        q[t] = make_float4(0.f, 0.f, 0.f, 0.f);
        if (t < nr) {
            int r = wid + t * 8;
            int node = r / 17, sub = r - node * 17;
            long gnode = (long)blockIdx.x * NPB + node;
            if (gnode < n) {
                const float4* src = (sub == 0)
                    ? (const float4*)(x + gnode * (long)F)
                    : (const float4*)(nb + (gnode * 16 + (sub - 1)) * (long)F);
                q[t] = src[lane];
            }
        }
    }

    // ---- B tiles: W1 [64][128] -> fp16 hi/lo, swizzled ----
    const float4* W1v = (const float4*)W1;
    #pragma unroll
    for (int t = 0; t < 8; t++) {
        int gi = tid + t * THREADS;        // gi = j*32 + f4
        int j = gi >> 5, f4 = gi & 31;     // f4: quad (8B = half chunk)
        float4 v = W1v[gi];
        __half h0, h1, h2, h3, l0, l1, l2, l3;
        cvt_hilo(v.x, h0, l0); cvt_hilo(v.y, h1, l1);
        cvt_hilo(v.z, h2, l2); cvt_hilo(v.w, h3, l3);
        uint32_t off = sw_off(j, f4 >> 1) + (uint32_t)(f4 & 1) * 8u;
        *(uint2*)(sm + SM_BHI + off) = pack4(h0, h1, h2, h3);
        *(uint2*)(sm + SM_BLO + off) = pack4(l0, l1, l2, l3);
    }

    // ---- small weights: W2^T [j][m], Wc^T [m][c] ----
    for (int i2 = tid; i2 < H1 * H2; i2 += THREADS) {
        int m = i2 >> 6, j = i2 & 63;
        ((float*)(sm + SM_W2T))[j * H2 + m] = W2[i2];
    }
    for (int i2 = tid; i2 < H2 * NC; i2 += THREADS) {
        int c = i2 >> 5, m = i2 & 31;
        ((float*)(sm + SM_WCT))[m * NC + c] = Wc[i2];
    }

    // ---- A: l2-normalize, split fp16 hi/lo, store swizzled ----
    #pragma unroll
    for (int t = 0; t < 15; t++) {
        if (t < nr) {
            int r = wid + t * 8;
            float4 v = q[t];
            float ss = v.x * v.x + v.y * v.y + v.z * v.z + v.w * v.w;
            #pragma unroll
            for (int o = 16; o > 0; o >>= 1) ss += __shfl_xor_sync(0xffffffffu, ss, o);
            float inv = 1.f / fmaxf(sqrtf(ss), 1e-12f);
            __half h0, h1, h2, h3, l0, l1, l2, l3;
            cvt_hilo(v.x * inv, h0, l0); cvt_hilo(v.y * inv, h1, l1);
            cvt_hilo(v.z * inv, h2, l2); cvt_hilo(v.w * inv, h3, l3);
            uint32_t off = sw_off(r, lane >> 1) + (uint32_t)(lane & 1) * 8u;
            *(uint2*)(sm + SM_AHI + off) = pack4(h0, h1, h2, h3);
            *(uint2*)(sm + SM_ALO + off) = pack4(l0, l1, l2, l3);
        }
    }

    // ---- zero padding rows 119..127 (9 rows x 16 chunks, hi & lo) ----
    if (tid < 144) {
        int r = RV + tid / 16, ch = tid & 15;
        uint32_t off = sw_off(r, ch);
        *(uint4*)(sm + SM_AHI + off) = make_uint4(0, 0, 0, 0);
        *(uint4*)(sm + SM_ALO + off) = make_uint4(0, 0, 0, 0);
    }
    __syncthreads();

    // ---- GEMM: warp grid 4(M) x 2(N); warp tile M=32 x N=32 ----
    // D = Ahi*Bhi^T + Ahi*Blo^T + Alo*Bhi^T (fp32 accum)
    const int wm = wid >> 1, wn = wid & 1;
    float acc[2][4][4];     // [m-subtile][n-tile(8)][frag]
    #pragma unroll
    for (int m = 0; m < 2; m++)
        #pragma unroll
        for (int ntl = 0; ntl < 4; ntl++)
            acc[m][ntl][0] = acc[m][ntl][1] = acc[m][ntl][2] = acc[m][ntl][3] = 0.f;

    {
        const int arow = 32 * wm + (lane & 15);
        const int asel = lane >> 4;                      // 0: k0-7, 1: k8-15
        const int bn_local = 32 * wn + ((lane >> 4) << 3) + (lane & 7);
        const int bsel = (lane >> 3) & 1;

        #pragma unroll
        for (int kc = 0; kc < 8; kc++) {
            uint32_t ahi[2][4], alo[2][4];
            #pragma unroll
            for (int m = 0; m < 2; m++) {
                uint32_t aoff = sw_off(arow + 16 * m, kc * 2 + asel);
                ldsm_x4(ahi[m], sb + SM_AHI + aoff);
                ldsm_x4(alo[m], sb + SM_ALO + aoff);
            }
            uint32_t bhi[2][4], blo[2][4];               // pair p -> n-tiles 2p, 2p+1
            #pragma unroll
            for (int p = 0; p < 2; p++) {
                uint32_t boff = sw_off(bn_local + 16 * p, kc * 2 + bsel);
                ldsm_x4(bhi[p], sb + SM_BHI + boff);
                ldsm_x4(blo[p], sb + SM_BLO + boff);
            }
            // group-outer: each acc's dependent MMAs are 8 issues apart
            #pragma unroll
            for (int g = 0; g < 3; g++) {
                #pragma unroll
                for (int m = 0; m < 2; m++) {
                    #pragma unroll
                    for (int ntl = 0; ntl < 4; ntl++) {
                        const uint32_t* a = (g == 2) ? alo[m] : ahi[m];
                        const uint32_t* b = (g == 1) ? (blo[ntl >> 1] + (ntl & 1) * 2)
                                                     : (bhi[ntl >> 1] + (ntl & 1) * 2);
                        mma16816(acc[m][ntl], a, b);
                    }
                }
            }
        }
    }
    __syncthreads();   // done reading A/B tiles; Hbuf overlays them

    // ---- write C frags to Hbuf[128][65] ----
    float* hb = (float*)(sm + SM_HB);
    {
        #pragma unroll
        for (int m = 0; m < 2; m++) {
            int r0 = 32 * wm + 16 * m + (lane >> 2);
            int c0 = 32 * wn + (lane & 3) * 2;
            #pragma unroll
            for (int ntl = 0; ntl < 4; ntl++) {
                int c = c0 + ntl * 8;
                hb[r0 * 65 + c]           = acc[m][ntl][0];
                hb[r0 * 65 + c + 1]       = acc[m][ntl][1];
                hb[(r0 + 8) * 65 + c]     = acc[m][ntl][2];
                hb[(r0 + 8) * 65 + c + 1] = acc[m][ntl][3];
            }
        }
    }
    __syncthreads();

    // ---- per-node epilogue ----
    long gnode = (long)blockIdx.x * NPB + wid;
    if (wid < NPB && gnode < n) {
        int base = wid * 17;
        float hx0 = hb[base * 65 + lane], hx1 = hb[base * 65 + 32 + lane];
        float r0 = 0.f, r1 = 0.f;
        #pragma unroll
        for (int k = 0; k < 16; k++) {
            const float* hr = hb + (base + 1 + k) * 65;
            r0 += fmaxf(hx0 + hr[lane], 0.f);
            r1 += fmaxf(hx1 + hr[32 + lane], 0.f);
        }
        float* rb = (float*)(sm + SM_RBUF) + wid * 64;
        rb[lane] = r0;
        rb[lane + 32] = r1;
        __syncwarp();
        const float* W2t = (const float*)(sm + SM_W2T);
        float y = 0.f;
        #pragma unroll
        for (int j = 0; j < H1; j++) y += rb[j] * W2t[j * H2 + lane];
        y = fmaxf(y, 0.f);
        float* yb = (float*)(sm + SM_YBUF) + wid * 32;
        yb[lane] = y;
        __syncwarp();
        if (lane < NC) {
            const float* Wct = (const float*)(sm + SM_WCT);
            float o = 0.f;
            #pragma unroll
            for (int m2 = 0; m2 < H2; m2++) o += yb[m2] * Wct[m2 * NC + lane];
            out[gnode * NC + lane] = o;
        }
    }
}

extern "C" void kernel_launch(void* const* d_in, const int* in_sizes, int n_in,
                              void* d_out, int out_size)
{
    const float* x  = (const float*)d_in[0];
    const float* nb = (const float*)d_in[1];
    const float* W1 = (const float*)d_in[2];
    const float* W2 = (const float*)d_in[3];
    const float* Wc = (const float*)d_in[4];
    float* out = (float*)d_out;

    int n = in_sizes[0] / F;
    cudaFuncSetAttribute(gcn_mma_kernel,
                         cudaFuncAttributeMaxDynamicSharedMemorySize, SM_TOTAL);
    int grid = (n + NPB - 1) / NPB;
    gcn_mma_kernel<<<grid, THREADS, SM_TOTAL>>>(x, nb, W1, W2, Wc, out, n);
}

// round 6
// speedup vs baseline: 1.9925x; 1.3360x over previous
#include <cuda_runtime.h>
#include <cuda_fp16.h>
#include <stdint.h>

#define F    128
#define H1   64
#define H2   32
#define NC   10
#define NPB  7          // nodes per block
#define RV   119        // valid rows = 7*17
#define THREADS 256     // 8 warps: 4(M) x 2(N)

// ---- dynamic shared layout (main kernel) ----
#define SM_AHI  0            // 128x128 fp16 hi (32KB), swizzled
#define SM_ALO  32768        // lo (32KB)
#define SM_HB   0            // Hbuf 128x65 f32 (33280) overlays A after GEMM
#define SM_RBUF 36864        // 8*64*4, overlays ALO tail (post-GEMM only)
#define SM_YBUF 38912        // 8*32*4
#define SM_WCT  65536        // 1280 (live prologue->epilogue, after A tiles)
#define SM_TOTAL 66816

// precomputed W1 MMA fragments + transposed W2
__device__ uint4 gBhi[8 * 4 * 32];   // [kc][ntile tp][lane]
__device__ uint4 gBlo[8 * 4 * 32];
__device__ float gW2t[H1 * H2];      // [j][m]

// fp16 tile: row stride 256B, 16 chunks of 16B; swizzle chunk ^= (row&7)
static __device__ __forceinline__ uint32_t sw_off(int row, int chunk) {
    return (uint32_t)row * 256u + (uint32_t)((chunk ^ (row & 7)) << 4);
}
static __device__ __forceinline__ uint32_t smem_u32(const void* p) {
    uint32_t a;
    asm("{ .reg .u64 t; cvta.to.shared.u64 t, %1; cvt.u32.u64 %0, t; }" : "=r"(a) : "l"(p));
    return a;
}
static __device__ __forceinline__ void ldsm_x4(uint32_t* r, uint32_t addr) {
    asm volatile("ldmatrix.sync.aligned.m8n8.x4.shared.b16 {%0,%1,%2,%3}, [%4];"
                 : "=r"(r[0]), "=r"(r[1]), "=r"(r[2]), "=r"(r[3]) : "r"(addr));
}
static __device__ __forceinline__ void mma16816(float* c, const uint32_t* a,
                                                uint32_t b0, uint32_t b1) {
    asm volatile(
        "mma.sync.aligned.m16n8k16.row.col.f32.f16.f16.f32 "
        "{%0,%1,%2,%3}, {%4,%5,%6,%7}, {%8,%9}, {%0,%1,%2,%3};"
        : "+f"(c[0]), "+f"(c[1]), "+f"(c[2]), "+f"(c[3])
        : "r"(a[0]), "r"(a[1]), "r"(a[2]), "r"(a[3]), "r"(b0), "r"(b1));
}
static __device__ __forceinline__ void cvt_hilo(float v, __half& h, __half& l) {
    h = __float2half_rn(v);
    l = __float2half_rn(v - __half2float(h));
}
static __device__ __forceinline__ uint2 pack4(__half h0, __half h1, __half h2, __half h3) {
    __half2 a = __halves2half2(h0, h1);
    __half2 b = __halves2half2(h2, h3);
    uint2 r;
    r.x = *(const uint32_t*)&a;
    r.y = *(const uint32_t*)&b;
    return r;
}

// ---- init kernel: build W1 fragments (by replaying the ldsm path) + W2^T ----
__global__ void gcn_init_kernel(const float* __restrict__ W1,
                                const float* __restrict__ W2)
{
    __shared__ __align__(16) char bsm[32768];    // BHI 16K | BLO 16K
    const int tid = threadIdx.x, wid = tid >> 5, lane = tid & 31;

    const float4* W1v = (const float4*)W1;
    #pragma unroll
    for (int t = 0; t < 8; t++) {
        int gi = tid + t * 256;          // gi = j*32 + f4
        int j = gi >> 5, f4 = gi & 31;
        float4 v = W1v[gi];
        __half h0, h1, h2, h3, l0, l1, l2, l3;
        cvt_hilo(v.x, h0, l0); cvt_hilo(v.y, h1, l1);
        cvt_hilo(v.z, h2, l2); cvt_hilo(v.w, h3, l3);
        uint32_t off = sw_off(j, f4 >> 1) + (uint32_t)(f4 & 1) * 8u;
        *(uint2*)(bsm + off)         = pack4(h0, h1, h2, h3);
        *(uint2*)(bsm + 16384 + off) = pack4(l0, l1, l2, l3);
    }
    for (int idx = tid; idx < H1 * H2; idx += 256) {
        int m = idx >> 6, j = idx & 63;
        gW2t[j * H2 + m] = W2[idx];
    }
    __syncthreads();

    const uint32_t sb = smem_u32(bsm);
    const int kc = wid;                  // warp w -> k-chunk w
    #pragma unroll
    for (int tp = 0; tp < 4; tp++) {
        int row = 16 * tp + ((lane >> 4) << 3) + (lane & 7);
        int chunk = kc * 2 + ((lane >> 3) & 1);
        uint32_t off = sw_off(row, chunk);
        uint32_t rh[4], rl[4];
        ldsm_x4(rh, sb + off);
        ldsm_x4(rl, sb + 16384 + off);
        gBhi[(kc * 4 + tp) * 32 + lane] = make_uint4(rh[0], rh[1], rh[2], rh[3]);
        gBlo[(kc * 4 + tp) * 32 + lane] = make_uint4(rl[0], rl[1], rl[2], rl[3]);
    }
}

__global__ __launch_bounds__(THREADS, 3) void gcn_mma_kernel(
    const float* __restrict__ x,  const float* __restrict__ nb,
    const float* __restrict__ Wc, float* __restrict__ out, int n)
{
    extern __shared__ char sm[];
    const uint32_t sb = smem_u32(sm);
    const int tid = threadIdx.x, wid = tid >> 5, lane = tid & 31;
    const long gbase = (long)blockIdx.x * NPB;

    // ---- Wc^T [m][c] into smem ----
    for (int i2 = tid; i2 < H2 * NC; i2 += THREADS) {
        int c = i2 >> 5, m = i2 & 31;
        ((float*)(sm + SM_WCT))[m * NC + c] = Wc[i2];
    }

    // ---- A rows: warp w owns rows w + 8t (t<15), 3 batches of 5 (MLP=5) ----
    #pragma unroll 1
    for (int b0 = 0; b0 < 15; b0 += 5) {
        float4 q[5];
        #pragma unroll
        for (int t = 0; t < 5; t++) {
            int r = wid + (b0 + t) * 8;
            q[t] = make_float4(0.f, 0.f, 0.f, 0.f);
            if (r < RV) {
                int node = r / 17, sub = r - node * 17;
                long gnode = gbase + node;
                if (gnode < n) {
                    const float4* src = (sub == 0)
                        ? (const float4*)(x + gnode * (long)F)
                        : (const float4*)(nb + (gnode * 16 + (sub - 1)) * (long)F);
                    q[t] = src[lane];
                }
            }
        }
        #pragma unroll
        for (int t = 0; t < 5; t++) {
            int r = wid + (b0 + t) * 8;
            if (r < RV) {
                float4 v = q[t];
                float ss = v.x * v.x + v.y * v.y + v.z * v.z + v.w * v.w;
                #pragma unroll
                for (int o = 16; o > 0; o >>= 1) ss += __shfl_xor_sync(0xffffffffu, ss, o);
                float inv = 1.f / fmaxf(sqrtf(ss), 1e-12f);
                __half h0, h1, h2, h3, l0, l1, l2, l3;
                cvt_hilo(v.x * inv, h0, l0); cvt_hilo(v.y * inv, h1, l1);
                cvt_hilo(v.z * inv, h2, l2); cvt_hilo(v.w * inv, h3, l3);
                uint32_t off = sw_off(r, lane >> 1) + (uint32_t)(lane & 1) * 8u;
                *(uint2*)(sm + SM_AHI + off) = pack4(h0, h1, h2, h3);
                *(uint2*)(sm + SM_ALO + off) = pack4(l0, l1, l2, l3);
            }
        }
    }

    // ---- zero padding rows 119..127 ----
    if (tid < 144) {
        int r = RV + tid / 16, ch = tid & 15;
        uint32_t off = sw_off(r, ch);
        *(uint4*)(sm + SM_AHI + off) = make_uint4(0, 0, 0, 0);
        *(uint4*)(sm + SM_ALO + off) = make_uint4(0, 0, 0, 0);
    }
    __syncthreads();

    // ---- GEMM: warp grid 4(M) x 2(N); warp tile M=32 x N=32 ----
    // D = Ahi*Bhi^T + Alo*Bhi^T + Ahi*Blo^T (fp32 accum); B frags from gmem (L2-hot)
    const int wm = wid >> 1, wn = wid & 1;
    float acc[2][4][4];
    #pragma unroll
    for (int m = 0; m < 2; m++)
        #pragma unroll
        for (int ntl = 0; ntl < 4; ntl++)
            acc[m][ntl][0] = acc[m][ntl][1] = acc[m][ntl][2] = acc[m][ntl][3] = 0.f;

    {
        const int arow = 32 * wm + (lane & 15);
        const int asel = lane >> 4;
        const int tpb = 2 * wn;

        #pragma unroll
        for (int kc = 0; kc < 8; kc++) {
            uint4 bh0 = gBhi[(kc * 4 + tpb) * 32 + lane];
            uint4 bh1 = gBhi[(kc * 4 + tpb + 1) * 32 + lane];
            uint4 bl0 = gBlo[(kc * 4 + tpb) * 32 + lane];
            uint4 bl1 = gBlo[(kc * 4 + tpb + 1) * 32 + lane];

            uint32_t ahi[2][4], alo[2][4];
            #pragma unroll
            for (int m = 0; m < 2; m++) {
                uint32_t aoff = sw_off(arow + 16 * m, kc * 2 + asel);
                ldsm_x4(ahi[m], sb + SM_AHI + aoff);
                ldsm_x4(alo[m], sb + SM_ALO + aoff);
            }
            #pragma unroll
            for (int m = 0; m < 2; m++) {
                mma16816(acc[m][0], ahi[m], bh0.x, bh0.y);
                mma16816(acc[m][1], ahi[m], bh0.z, bh0.w);
                mma16816(acc[m][2], ahi[m], bh1.x, bh1.y);
                mma16816(acc[m][3], ahi[m], bh1.z, bh1.w);
            }
            #pragma unroll
            for (int m = 0; m < 2; m++) {
                mma16816(acc[m][0], alo[m], bh0.x, bh0.y);
                mma16816(acc[m][1], alo[m], bh0.z, bh0.w);
                mma16816(acc[m][2], alo[m], bh1.x, bh1.y);
                mma16816(acc[m][3], alo[m], bh1.z, bh1.w);
            }
            #pragma unroll
            for (int m = 0; m < 2; m++) {
                mma16816(acc[m][0], ahi[m], bl0.x, bl0.y);
                mma16816(acc[m][1], ahi[m], bl0.z, bl0.w);
                mma16816(acc[m][2], ahi[m], bl1.x, bl1.y);
                mma16816(acc[m][3], ahi[m], bl1.z, bl1.w);
            }
        }
    }
    __syncthreads();   // A tiles dead; Hbuf overlays them

    // ---- write C frags to Hbuf[128][65] ----
    float* hb = (float*)(sm + SM_HB);
    #pragma unroll
    for (int m = 0; m < 2; m++) {
        int r0 = 32 * wm + 16 * m + (lane >> 2);
        int c0 = 32 * wn + (lane & 3) * 2;
        #pragma unroll
        for (int ntl = 0; ntl < 4; ntl++) {
            int c = c0 + ntl * 8;
            hb[r0 * 65 + c]           = acc[m][ntl][0];
            hb[r0 * 65 + c + 1]       = acc[m][ntl][1];
            hb[(r0 + 8) * 65 + c]     = acc[m][ntl][2];
            hb[(r0 + 8) * 65 + c + 1] = acc[m][ntl][3];
        }
    }
    __syncthreads();

    // ---- per-node epilogue (W2^T streamed from gmem, L2-hot, coalesced) ----
    long gnode = gbase + wid;
    if (wid < NPB && gnode < n) {
        int base = wid * 17;
        float hx0 = hb[base * 65 + lane], hx1 = hb[base * 65 + 32 + lane];
        float r0 = 0.f, r1 = 0.f;
        #pragma unroll
        for (int k = 0; k < 16; k++) {
            const float* hr = hb + (base + 1 + k) * 65;
            r0 += fmaxf(hx0 + hr[lane], 0.f);
            r1 += fmaxf(hx1 + hr[32 + lane], 0.f);
        }
        float* rb = (float*)(sm + SM_RBUF) + wid * 64;
        rb[lane] = r0;
        rb[lane + 32] = r1;
        __syncwarp();
        float y = 0.f;
        #pragma unroll
        for (int j = 0; j < H1; j++) y += rb[j] * gW2t[j * H2 + lane];
        y = fmaxf(y, 0.f);
        float* yb = (float*)(sm + SM_YBUF) + wid * 32;
        yb[lane] = y;
        __syncwarp();
        if (lane < NC) {
            const float* Wct = (const float*)(sm + SM_WCT);
            float o = 0.f;
            #pragma unroll
            for (int m2 = 0; m2 < H2; m2++) o += yb[m2] * Wct[m2 * NC + lane];
            out[gnode * NC + lane] = o;
        }
    }
}

extern "C" void kernel_launch(void* const* d_in, const int* in_sizes, int n_in,
                              void* d_out, int out_size)
{
    const float* x  = (const float*)d_in[0];
    const float* nb = (const float*)d_in[1];
    const float* W1 = (const float*)d_in[2];
    const float* W2 = (const float*)d_in[3];
    const float* Wc = (const float*)d_in[4];
    float* out = (float*)d_out;

    int n = in_sizes[0] / F;
    gcn_init_kernel<<<1, 256>>>(W1, W2);
    cudaFuncSetAttribute(gcn_mma_kernel,
                         cudaFuncAttributeMaxDynamicSharedMemorySize, SM_TOTAL);
    int grid = (n + NPB - 1) / NPB;
    gcn_mma_kernel<<<grid, THREADS, SM_TOTAL>>>(x, nb, Wc, out, n);
}

// round 7
// speedup vs baseline: 1.9937x; 1.0006x over previous
#include <cuda_runtime.h>
#include <cuda_fp16.h>
#include <stdint.h>

#define F    128
#define H1   64
#define H2   32
#define NC   10
#define NPB  7          // nodes per block
#define RV   119        // valid rows = 7*17
#define THREADS 256     // 8 warps: 4(M) x 2(N)

// ---- dynamic shared layout (main kernel) ----
#define SM_AHI  0            // 128x128 fp16 hi (32KB), swizzled
#define SM_ALO  32768        // lo (32KB)
#define SM_HB   0            // Hbuf 128x65 f32 (33280) overlays A after GEMM
#define SM_RBUF 36864        // 8*64*4, overlays ALO tail (post-GEMM only)
#define SM_YBUF 38912        // 8*32*4
#define SM_WCT  65536        // 1280 (live prologue->epilogue, after A tiles)
#define SM_TOTAL 66816

// precomputed W1 MMA fragments + transposed W2
__device__ uint4 gBhi[8 * 4 * 32];   // [kc][ntile tp][lane]
__device__ uint4 gBlo[8 * 4 * 32];
__device__ float gW2t[H1 * H2];      // [j][m]

// fp16 tile: row stride 256B, 16 chunks of 16B; swizzle chunk ^= (row&7)
static __device__ __forceinline__ uint32_t sw_off(int row, int chunk) {
    return (uint32_t)row * 256u + (uint32_t)((chunk ^ (row & 7)) << 4);
}
static __device__ __forceinline__ uint32_t smem_u32(const void* p) {
    uint32_t a;
    asm("{ .reg .u64 t; cvta.to.shared.u64 t, %1; cvt.u32.u64 %0, t; }" : "=r"(a) : "l"(p));
    return a;
}
static __device__ __forceinline__ void ldsm_x4(uint32_t* r, uint32_t addr) {
    asm volatile("ldmatrix.sync.aligned.m8n8.x4.shared.b16 {%0,%1,%2,%3}, [%4];"
                 : "=r"(r[0]), "=r"(r[1]), "=r"(r[2]), "=r"(r[3]) : "r"(addr));
}
static __device__ __forceinline__ void mma16816(float* c, const uint32_t* a,
                                                uint32_t b0, uint32_t b1) {
    asm volatile(
        "mma.sync.aligned.m16n8k16.row.col.f32.f16.f16.f32 "
        "{%0,%1,%2,%3}, {%4,%5,%6,%7}, {%8,%9}, {%0,%1,%2,%3};"
        : "+f"(c[0]), "+f"(c[1]), "+f"(c[2]), "+f"(c[3])
        : "r"(a[0]), "r"(a[1]), "r"(a[2]), "r"(a[3]), "r"(b0), "r"(b1));
}
static __device__ __forceinline__ void cvt_hilo(float v, __half& h, __half& l) {
    h = __float2half_rn(v);
    l = __float2half_rn(v - __half2float(h));
}
static __device__ __forceinline__ uint2 pack4(__half h0, __half h1, __half h2, __half h3) {
    __half2 a = __halves2half2(h0, h1);
    __half2 b = __halves2half2(h2, h3);
    uint2 r;
    r.x = *(const uint32_t*)&a;
    r.y = *(const uint32_t*)&b;
    return r;
}

// ---- init kernel: build W1 fragments (by replaying the ldsm path) + W2^T ----
__global__ void gcn_init_kernel(const float* __restrict__ W1,
                                const float* __restrict__ W2)
{
    __shared__ __align__(16) char bsm[32768];    // BHI 16K | BLO 16K
    const int tid = threadIdx.x, wid = tid >> 5, lane = tid & 31;

    const float4* W1v = (const float4*)W1;
    #pragma unroll
    for (int t = 0; t < 8; t++) {
        int gi = tid + t * 256;          // gi = j*32 + f4
        int j = gi >> 5, f4 = gi & 31;
        float4 v = W1v[gi];
        __half h0, h1, h2, h3, l0, l1, l2, l3;
        cvt_hilo(v.x, h0, l0); cvt_hilo(v.y, h1, l1);
        cvt_hilo(v.z, h2, l2); cvt_hilo(v.w, h3, l3);
        uint32_t off = sw_off(j, f4 >> 1) + (uint32_t)(f4 & 1) * 8u;
        *(uint2*)(bsm + off)         = pack4(h0, h1, h2, h3);
        *(uint2*)(bsm + 16384 + off) = pack4(l0, l1, l2, l3);
    }
    for (int idx = tid; idx < H1 * H2; idx += 256) {
        int m = idx >> 6, j = idx & 63;
        gW2t[j * H2 + m] = W2[idx];
    }
    __syncthreads();

    const uint32_t sb = smem_u32(bsm);
    const int kc = wid;                  // warp w -> k-chunk w
    #pragma unroll
    for (int tp = 0; tp < 4; tp++) {
        int row = 16 * tp + ((lane >> 4) << 3) + (lane & 7);
        int chunk = kc * 2 + ((lane >> 3) & 1);
        uint32_t off = sw_off(row, chunk);
        uint32_t rh[4], rl[4];
        ldsm_x4(rh, sb + off);
        ldsm_x4(rl, sb + 16384 + off);
        gBhi[(kc * 4 + tp) * 32 + lane] = make_uint4(rh[0], rh[1], rh[2], rh[3]);
        gBlo[(kc * 4 + tp) * 32 + lane] = make_uint4(rl[0], rl[1], rl[2], rl[3]);
    }
}

__global__ __launch_bounds__(THREADS, 3) void gcn_mma_kernel(
    const float* __restrict__ x,  const float* __restrict__ nb,
    const float* __restrict__ Wc, float* __restrict__ out, int n)
{
    extern __shared__ char sm[];
    const uint32_t sb = smem_u32(sm);
    const int tid = threadIdx.x, wid = tid >> 5, lane = tid & 31;
    const long gbase = (long)blockIdx.x * NPB;

    // ---- Wc^T [m][c] into smem ----
    for (int i2 = tid; i2 < H2 * NC; i2 += THREADS) {
        int c = i2 >> 5, m = i2 & 31;
        ((float*)(sm + SM_WCT))[m * NC + c] = Wc[i2];
    }

    // ---- A rows: warp w owns rows w + 8t (t<15), 3 batches of 5 (MLP=5) ----
    #pragma unroll 1
    for (int b0 = 0; b0 < 15; b0 += 5) {
        float4 q[5];
        #pragma unroll
        for (int t = 0; t < 5; t++) {
            int r = wid + (b0 + t) * 8;
            q[t] = make_float4(0.f, 0.f, 0.f, 0.f);
            if (r < RV) {
                int node = r / 17, sub = r - node * 17;
                long gnode = gbase + node;
                if (gnode < n) {
                    const float4* src = (sub == 0)
                        ? (const float4*)(x + gnode * (long)F)
                        : (const float4*)(nb + (gnode * 16 + (sub - 1)) * (long)F);
                    q[t] = src[lane];
                }
            }
        }
        #pragma unroll
        for (int t = 0; t < 5; t++) {
            int r = wid + (b0 + t) * 8;
            if (r < RV) {
                float4 v = q[t];
                float ss = v.x * v.x + v.y * v.y + v.z * v.z + v.w * v.w;
                #pragma unroll
                for (int o = 16; o > 0; o >>= 1) ss += __shfl_xor_sync(0xffffffffu, ss, o);
                float inv = 1.f / fmaxf(sqrtf(ss), 1e-12f);
                __half h0, h1, h2, h3, l0, l1, l2, l3;
                cvt_hilo(v.x * inv, h0, l0); cvt_hilo(v.y * inv, h1, l1);
                cvt_hilo(v.z * inv, h2, l2); cvt_hilo(v.w * inv, h3, l3);
                uint32_t off = sw_off(r, lane >> 1) + (uint32_t)(lane & 1) * 8u;
                *(uint2*)(sm + SM_AHI + off) = pack4(h0, h1, h2, h3);
                *(uint2*)(sm + SM_ALO + off) = pack4(l0, l1, l2, l3);
            }
        }
    }

    // ---- zero padding rows 119..127 ----
    if (tid < 144) {
        int r = RV + tid / 16, ch = tid & 15;
        uint32_t off = sw_off(r, ch);
        *(uint4*)(sm + SM_AHI + off) = make_uint4(0, 0, 0, 0);
        *(uint4*)(sm + SM_ALO + off) = make_uint4(0, 0, 0, 0);
    }
    __syncthreads();

    // ---- GEMM: warp grid 4(M) x 2(N); warp tile M=32 x N=32 ----
    // D = Ahi*Bhi^T + Alo*Bhi^T + Ahi*Blo^T (fp32 accum)
    // B frags from gmem (L2-hot), Bhi double-buffered across kc, Blo issued early
    const int wm = wid >> 1, wn = wid & 1;
    float acc[2][4][4];
    #pragma unroll
    for (int m = 0; m < 2; m++)
        #pragma unroll
        for (int ntl = 0; ntl < 4; ntl++)
            acc[m][ntl][0] = acc[m][ntl][1] = acc[m][ntl][2] = acc[m][ntl][3] = 0.f;

    {
        const int arow = 32 * wm + (lane & 15);
        const int asel = lane >> 4;
        const int tpb = 2 * wn;
        const uint4* pBhi = gBhi + tpb * 32 + lane;
        const uint4* pBlo = gBlo + tpb * 32 + lane;

        uint4 bh0 = pBhi[0];
        uint4 bh1 = pBhi[32];

        #pragma unroll
        for (int kc = 0; kc < 8; kc++) {
            // issue Blo(kc) now; consumed after 4 LDSM + 16 MMAs
            uint4 bl0 = pBlo[kc * 128];
            uint4 bl1 = pBlo[kc * 128 + 32];
            // prefetch Bhi(kc+1); consumed next iteration
            uint4 nh0, nh1;
            if (kc < 7) {
                nh0 = pBhi[(kc + 1) * 128];
                nh1 = pBhi[(kc + 1) * 128 + 32];
            }

            uint32_t ahi[2][4], alo[2][4];
            #pragma unroll
            for (int m = 0; m < 2; m++) {
                uint32_t aoff = sw_off(arow + 16 * m, kc * 2 + asel);
                ldsm_x4(ahi[m], sb + SM_AHI + aoff);
                ldsm_x4(alo[m], sb + SM_ALO + aoff);
            }
            #pragma unroll
            for (int m = 0; m < 2; m++) {
                mma16816(acc[m][0], ahi[m], bh0.x, bh0.y);
                mma16816(acc[m][1], ahi[m], bh0.z, bh0.w);
                mma16816(acc[m][2], ahi[m], bh1.x, bh1.y);
                mma16816(acc[m][3], ahi[m], bh1.z, bh1.w);
            }
            #pragma unroll
            for (int m = 0; m < 2; m++) {
                mma16816(acc[m][0], alo[m], bh0.x, bh0.y);
                mma16816(acc[m][1], alo[m], bh0.z, bh0.w);
                mma16816(acc[m][2], alo[m], bh1.x, bh1.y);
                mma16816(acc[m][3], alo[m], bh1.z, bh1.w);
            }
            #pragma unroll
            for (int m = 0; m < 2; m++) {
                mma16816(acc[m][0], ahi[m], bl0.x, bl0.y);
                mma16816(acc[m][1], ahi[m], bl0.z, bl0.w);
                mma16816(acc[m][2], ahi[m], bl1.x, bl1.y);
                mma16816(acc[m][3], ahi[m], bl1.z, bl1.w);
            }
            if (kc < 7) { bh0 = nh0; bh1 = nh1; }
        }
    }
    __syncthreads();   // A tiles dead; Hbuf overlays them

    // ---- write C frags to Hbuf[128][65] ----
    float* hb = (float*)(sm + SM_HB);
    #pragma unroll
    for (int m = 0; m < 2; m++) {
        int r0 = 32 * wm + 16 * m + (lane >> 2);
        int c0 = 32 * wn + (lane & 3) * 2;
        #pragma unroll
        for (int ntl = 0; ntl < 4; ntl++) {
            int c = c0 + ntl * 8;
            hb[r0 * 65 + c]           = acc[m][ntl][0];
            hb[r0 * 65 + c + 1]       = acc[m][ntl][1];
            hb[(r0 + 8) * 65 + c]     = acc[m][ntl][2];
            hb[(r0 + 8) * 65 + c + 1] = acc[m][ntl][3];
        }
    }
    __syncthreads();

    // ---- per-node epilogue (W2^T streamed from gmem, L2-hot, coalesced) ----
    long gnode = gbase + wid;
    if (wid < NPB && gnode < n) {
        int base = wid * 17;
        float hx0 = hb[base * 65 + lane], hx1 = hb[base * 65 + 32 + lane];
        float r0 = 0.f, r1 = 0.f;
        #pragma unroll
        for (int k = 0; k < 16; k++) {
            const float* hr = hb + (base + 1 + k) * 65;
            r0 += fmaxf(hx0 + hr[lane], 0.f);
            r1 += fmaxf(hx1 + hr[32 + lane], 0.f);
        }
        float* rb = (float*)(sm + SM_RBUF) + wid * 64;
        rb[lane] = r0;
        rb[lane + 32] = r1;
        __syncwarp();
        float y = 0.f;
        #pragma unroll
        for (int j = 0; j < H1; j++) y += rb[j] * gW2t[j * H2 + lane];
        y = fmaxf(y, 0.f);
        float* yb = (float*)(sm + SM_YBUF) + wid * 32;
        yb[lane] = y;
        __syncwarp();
        if (lane < NC) {
            const float* Wct = (const float*)(sm + SM_WCT);
            float o = 0.f;
            #pragma unroll
            for (int m2 = 0; m2 < H2; m2++) o += yb[m2] * Wct[m2 * NC + lane];
            out[gnode * NC + lane] = o;
        }
    }
}

extern "C" void kernel_launch(void* const* d_in, const int* in_sizes, int n_in,
                              void* d_out, int out_size)
{
    const float* x  = (const float*)d_in[0];
    const float* nb = (const float*)d_in[1];
    const float* W1 = (const float*)d_in[2];
    const float* W2 = (const float*)d_in[3];
    const float* Wc = (const float*)d_in[4];
    float* out = (float*)d_out;

    int n = in_sizes[0] / F;
    gcn_init_kernel<<<1, 256>>>(W1, W2);
    cudaFuncSetAttribute(gcn_mma_kernel,
                         cudaFuncAttributeMaxDynamicSharedMemorySize, SM_TOTAL);
    int grid = (n + NPB - 1) / NPB;
    gcn_mma_kernel<<<grid, THREADS, SM_TOTAL>>>(x, nb, Wc, out, n);
}

// round 8
// speedup vs baseline: 2.4685x; 1.2382x over previous
#include <cuda_runtime.h>
#include <cuda_fp16.h>
#include <stdint.h>

#define F    128
#define H1   64
#define H2   32
#define NC   10
#define NPB  7          // nodes per block
#define RV   119        // valid rows = 7*17
#define THREADS 256     // 8 warps: 4(M) x 2(N)

// ---- dynamic shared layout ----
#define SM_AHI  0            // 128x128 fp16 hi (32KB), swizzled
#define SM_HB   0            // Hbuf 128x65 f32 (33280) overlays AHI after GEMM
#define SM_RBUF 33280        // 8*64*4
#define SM_YBUF 35328        // 8*32*4
#define SM_WCT  36352        // 1280
#define SM_TOTAL 37632       // -> 4 CTAs/SM (smem & 64-reg cap)

// precomputed W1 MMA fragments + transposed W2
__device__ uint4 gBhi[8 * 4 * 32];   // [kc][ntile tp][lane]
__device__ uint4 gBlo[8 * 4 * 32];
__device__ float gW2t[H1 * H2];      // [j][m]

// fp16 tile: row stride 256B, 16 chunks of 16B; swizzle chunk ^= (row&7)
static __device__ __forceinline__ uint32_t sw_off(int row, int chunk) {
    return (uint32_t)row * 256u + (uint32_t)((chunk ^ (row & 7)) << 4);
}
static __device__ __forceinline__ uint32_t smem_u32(const void* p) {
    uint32_t a;
    asm("{ .reg .u64 t; cvta.to.shared.u64 t, %1; cvt.u32.u64 %0, t; }" : "=r"(a) : "l"(p));
    return a;
}
static __device__ __forceinline__ void ldsm_x4(uint32_t* r, uint32_t addr) {
    asm volatile("ldmatrix.sync.aligned.m8n8.x4.shared.b16 {%0,%1,%2,%3}, [%4];"
                 : "=r"(r[0]), "=r"(r[1]), "=r"(r[2]), "=r"(r[3]) : "r"(addr));
}
static __device__ __forceinline__ void mma16816(float* c, const uint32_t* a,
                                                uint32_t b0, uint32_t b1) {
    asm volatile(
        "mma.sync.aligned.m16n8k16.row.col.f32.f16.f16.f32 "
        "{%0,%1,%2,%3}, {%4,%5,%6,%7}, {%8,%9}, {%0,%1,%2,%3};"
        : "+f"(c[0]), "+f"(c[1]), "+f"(c[2]), "+f"(c[3])
        : "r"(a[0]), "r"(a[1]), "r"(a[2]), "r"(a[3]), "r"(b0), "r"(b1));
}
static __device__ __forceinline__ void cvt_hilo(float v, __half& h, __half& l) {
    h = __float2half_rn(v);
    l = __float2half_rn(v - __half2float(h));
}
static __device__ __forceinline__ uint2 pack4(__half h0, __half h1, __half h2, __half h3) {
    __half2 a = __halves2half2(h0, h1);
    __half2 b = __halves2half2(h2, h3);
    uint2 r;
    r.x = *(const uint32_t*)&a;
    r.y = *(const uint32_t*)&b;
    return r;
}

// ---- init kernel: build W1 hi/lo fragments (replaying the ldsm path) + W2^T ----
__global__ void gcn_init_kernel(const float* __restrict__ W1,
                                const float* __restrict__ W2)
{
    __shared__ __align__(16) char bsm[32768];    // BHI 16K | BLO 16K
    const int tid = threadIdx.x, wid = tid >> 5, lane = tid & 31;

    const float4* W1v = (const float4*)W1;
    #pragma unroll
    for (int t = 0; t < 8; t++) {
        int gi = tid + t * 256;          // gi = j*32 + f4
        int j = gi >> 5, f4 = gi & 31;
        float4 v = W1v[gi];
        __half h0, h1, h2, h3, l0, l1, l2, l3;
        cvt_hilo(v.x, h0, l0); cvt_hilo(v.y, h1, l1);
        cvt_hilo(v.z, h2, l2); cvt_hilo(v.w, h3, l3);
        uint32_t off = sw_off(j, f4 >> 1) + (uint32_t)(f4 & 1) * 8u;
        *(uint2*)(bsm + off)         = pack4(h0, h1, h2, h3);
        *(uint2*)(bsm + 16384 + off) = pack4(l0, l1, l2, l3);
    }
    for (int idx = tid; idx < H1 * H2; idx += 256) {
        int m = idx >> 6, j = idx & 63;
        gW2t[j * H2 + m] = W2[idx];
    }
    __syncthreads();

    const uint32_t sb = smem_u32(bsm);
    const int kc = wid;                  // warp w -> k-chunk w
    #pragma unroll
    for (int tp = 0; tp < 4; tp++) {
        int row = 16 * tp + ((lane >> 4) << 3) + (lane & 7);
        int chunk = kc * 2 + ((lane >> 3) & 1);
        uint32_t off = sw_off(row, chunk);
        uint32_t rh[4], rl[4];
        ldsm_x4(rh, sb + off);
        ldsm_x4(rl, sb + 16384 + off);
        gBhi[(kc * 4 + tp) * 32 + lane] = make_uint4(rh[0], rh[1], rh[2], rh[3]);
        gBlo[(kc * 4 + tp) * 32 + lane] = make_uint4(rl[0], rl[1], rl[2], rl[3]);
    }
}

__global__ __launch_bounds__(THREADS, 4) void gcn_mma_kernel(
    const float* __restrict__ x,  const float* __restrict__ nb,
    const float* __restrict__ Wc, float* __restrict__ out, int n)
{
    extern __shared__ char sm[];
    const uint32_t sb = smem_u32(sm);
    const int tid = threadIdx.x, wid = tid >> 5, lane = tid & 31;
    const long gbase = (long)blockIdx.x * NPB;

    // ---- Wc^T [m][c] into smem ----
    for (int i2 = tid; i2 < H2 * NC; i2 += THREADS) {
        int c = i2 >> 5, m = i2 & 31;
        ((float*)(sm + SM_WCT))[m * NC + c] = Wc[i2];
    }

    // ---- A rows: warp w owns rows w + 8t (t<15), 3 batches of 5 (MLP=5) ----
    #pragma unroll 1
    for (int b0 = 0; b0 < 15; b0 += 5) {
        float4 q[5];
        #pragma unroll
        for (int t = 0; t < 5; t++) {
            int r = wid + (b0 + t) * 8;
            q[t] = make_float4(0.f, 0.f, 0.f, 0.f);
            if (r < RV) {
                int node = r / 17, sub = r - node * 17;
                long gnode = gbase + node;
                if (gnode < n) {
                    const float4* src = (sub == 0)
                        ? (const float4*)(x + gnode * (long)F)
                        : (const float4*)(nb + (gnode * 16 + (sub - 1)) * (long)F);
                    q[t] = src[lane];
                }
            }
        }
        #pragma unroll
        for (int t = 0; t < 5; t++) {
            int r = wid + (b0 + t) * 8;
            if (r < RV) {
                float4 v = q[t];
                float ss = v.x * v.x + v.y * v.y + v.z * v.z + v.w * v.w;
                #pragma unroll
                for (int o = 16; o > 0; o >>= 1) ss += __shfl_xor_sync(0xffffffffu, ss, o);
                float inv = 1.f / fmaxf(sqrtf(ss), 1e-12f);
                __half h0 = __float2half_rn(v.x * inv);
                __half h1 = __float2half_rn(v.y * inv);
                __half h2 = __float2half_rn(v.z * inv);
                __half h3 = __float2half_rn(v.w * inv);
                uint32_t off = sw_off(r, lane >> 1) + (uint32_t)(lane & 1) * 8u;
                *(uint2*)(sm + SM_AHI + off) = pack4(h0, h1, h2, h3);
            }
        }
    }

    // ---- zero padding rows 119..127 ----
    if (tid < 144) {
        int r = RV + tid / 16, ch = tid & 15;
        *(uint4*)(sm + SM_AHI + sw_off(r, ch)) = make_uint4(0, 0, 0, 0);
    }
    __syncthreads();

    // ---- GEMM: warp grid 4(M) x 2(N); warp tile M=32 x N=32 ----
    // D = Ahi*Bhi^T + Ahi*Blo^T (fp32 accum); B frags from gmem (L2-hot)
    const int wm = wid >> 1, wn = wid & 1;
    float acc[2][4][4];
    #pragma unroll
    for (int m = 0; m < 2; m++)
        #pragma unroll
        for (int ntl = 0; ntl < 4; ntl++)
            acc[m][ntl][0] = acc[m][ntl][1] = acc[m][ntl][2] = acc[m][ntl][3] = 0.f;

    {
        const int arow = 32 * wm + (lane & 15);
        const int asel = lane >> 4;
        const int tpb = 2 * wn;
        const uint4* pBhi = gBhi + tpb * 32 + lane;
        const uint4* pBlo = gBlo + tpb * 32 + lane;

        #pragma unroll
        for (int kc = 0; kc < 8; kc++) {
            uint4 bh0 = pBhi[kc * 128];
            uint4 bh1 = pBhi[kc * 128 + 32];
            uint4 bl0 = pBlo[kc * 128];
            uint4 bl1 = pBlo[kc * 128 + 32];

            uint32_t ahi[2][4];
            #pragma unroll
            for (int m = 0; m < 2; m++)
                ldsm_x4(ahi[m], sb + SM_AHI + sw_off(arow + 16 * m, kc * 2 + asel));

            #pragma unroll
            for (int m = 0; m < 2; m++) {
                mma16816(acc[m][0], ahi[m], bh0.x, bh0.y);
                mma16816(acc[m][1], ahi[m], bh0.z, bh0.w);
                mma16816(acc[m][2], ahi[m], bh1.x, bh1.y);
                mma16816(acc[m][3], ahi[m], bh1.z, bh1.w);
            }
            #pragma unroll
            for (int m = 0; m < 2; m++) {
                mma16816(acc[m][0], ahi[m], bl0.x, bl0.y);
                mma16816(acc[m][1], ahi[m], bl0.z, bl0.w);
                mma16816(acc[m][2], ahi[m], bl1.x, bl1.y);
                mma16816(acc[m][3], ahi[m], bl1.z, bl1.w);
            }
        }
    }
    __syncthreads();   // A tile dead; Hbuf overlays it

    // ---- write C frags to Hbuf[128][65] ----
    float* hb = (float*)(sm + SM_HB);
    #pragma unroll
    for (int m = 0; m < 2; m++) {
        int r0 = 32 * wm + 16 * m + (lane >> 2);
        int c0 = 32 * wn + (lane & 3) * 2;
        #pragma unroll
        for (int ntl = 0; ntl < 4; ntl++) {
            int c = c0 + ntl * 8;
            hb[r0 * 65 + c]           = acc[m][ntl][0];
            hb[r0 * 65 + c + 1]       = acc[m][ntl][1];
            hb[(r0 + 8) * 65 + c]     = acc[m][ntl][2];
            hb[(r0 + 8) * 65 + c + 1] = acc[m][ntl][3];
        }
    }
    __syncthreads();

    // ---- per-node epilogue (W2^T streamed from gmem, L2-hot, coalesced) ----
    long gnode = gbase + wid;
    if (wid < NPB && gnode < n) {
        int base = wid * 17;
        float hx0 = hb[base * 65 + lane], hx1 = hb[base * 65 + 32 + lane];
        float r0 = 0.f, r1 = 0.f;
        #pragma unroll
        for (int k = 0; k < 16; k++) {
            const float* hr = hb + (base + 1 + k) * 65;
            r0 += fmaxf(hx0 + hr[lane], 0.f);
            r1 += fmaxf(hx1 + hr[32 + lane], 0.f);
        }
        float* rb = (float*)(sm + SM_RBUF) + wid * 64;
        rb[lane] = r0;
        rb[lane + 32] = r1;
        __syncwarp();
        float y = 0.f;
        #pragma unroll
        for (int j = 0; j < H1; j++) y += rb[j] * gW2t[j * H2 + lane];
        y = fmaxf(y, 0.f);
        float* yb = (float*)(sm + SM_YBUF) + wid * 32;
        yb[lane] = y;
        __syncwarp();
        if (lane < NC) {
            const float* Wct = (const float*)(sm + SM_WCT);
            float o = 0.f;
            #pragma unroll
            for (int m2 = 0; m2 < H2; m2++) o += yb[m2] * Wct[m2 * NC + lane];
            out[gnode * NC + lane] = o;
        }
    }
}

extern "C" void kernel_launch(void* const* d_in, const int* in_sizes, int n_in,
                              void* d_out, int out_size)
{
    const float* x  = (const float*)d_in[0];
    const float* nb = (const float*)d_in[1];
    const float* W1 = (const float*)d_in[2];
    const float* W2 = (const float*)d_in[3];
    const float* Wc = (const float*)d_in[4];
    float* out = (float*)d_out;

    int n = in_sizes[0] / F;
    gcn_init_kernel<<<1, 256>>>(W1, W2);
    cudaFuncSetAttribute(gcn_mma_kernel,
                         cudaFuncAttributeMaxDynamicSharedMemorySize, SM_TOTAL);
    int grid = (n + NPB - 1) / NPB;
    gcn_mma_kernel<<<grid, THREADS, SM_TOTAL>>>(x, nb, Wc, out, n);
}

// round 9
// speedup vs baseline: 2.7998x; 1.1342x over previous
#include <cuda_runtime.h>
#include <cuda_fp16.h>
#include <stdint.h>

#define F    128
#define H1   64
#define H2   32
#define NC   10
#define NPB  7          // nodes per block
#define RV   119        // valid rows = 7*17
#define THREADS 256     // 8 warps: 4(M) x 2(N)

// ---- dynamic shared layout ----
#define SM_AHI  0            // 128x128 fp16 hi (32KB), swizzled
#define SM_HB   0            // Hbuf 128x65 f32 (33280) overlays AHI after GEMM
#define SM_RBUF 33280        // 8*64*4
#define SM_YBUF 35328        // 8*32*4
#define SM_WCT  36352        // 1280
#define SM_TOTAL 37632       // -> 4 CTAs/SM (smem & 64-reg cap)

// precomputed W1 MMA fragments + transposed W2
__device__ uint4 gBhi[8 * 4 * 32];   // [kc][ntile tp][lane]
__device__ float gW2t[H1 * H2];      // [j][m]

// fp16 tile: row stride 256B, 16 chunks of 16B; swizzle chunk ^= (row&7)
static __device__ __forceinline__ uint32_t sw_off(int row, int chunk) {
    return (uint32_t)row * 256u + (uint32_t)((chunk ^ (row & 7)) << 4);
}
static __device__ __forceinline__ uint32_t smem_u32(const void* p) {
    uint32_t a;
    asm("{ .reg .u64 t; cvta.to.shared.u64 t, %1; cvt.u32.u64 %0, t; }" : "=r"(a) : "l"(p));
    return a;
}
static __device__ __forceinline__ void ldsm_x4(uint32_t* r, uint32_t addr) {
    asm volatile("ldmatrix.sync.aligned.m8n8.x4.shared.b16 {%0,%1,%2,%3}, [%4];"
                 : "=r"(r[0]), "=r"(r[1]), "=r"(r[2]), "=r"(r[3]) : "r"(addr));
}
static __device__ __forceinline__ void mma16816(float* c, const uint32_t* a,
                                                uint32_t b0, uint32_t b1) {
    asm volatile(
        "mma.sync.aligned.m16n8k16.row.col.f32.f16.f16.f32 "
        "{%0,%1,%2,%3}, {%4,%5,%6,%7}, {%8,%9}, {%0,%1,%2,%3};"
        : "+f"(c[0]), "+f"(c[1]), "+f"(c[2]), "+f"(c[3])
        : "r"(a[0]), "r"(a[1]), "r"(a[2]), "r"(a[3]), "r"(b0), "r"(b1));
}
static __device__ __forceinline__ uint2 pack4(__half h0, __half h1, __half h2, __half h3) {
    __half2 a = __halves2half2(h0, h1);
    __half2 b = __halves2half2(h2, h3);
    uint2 r;
    r.x = *(const uint32_t*)&a;
    r.y = *(const uint32_t*)&b;
    return r;
}

// ---- init kernel: build W1 fp16 fragments (replaying the ldsm path) + W2^T ----
__global__ void gcn_init_kernel(const float* __restrict__ W1,
                                const float* __restrict__ W2)
{
    __shared__ __align__(16) char bsm[16384];    // BHI 16K
    const int tid = threadIdx.x, wid = tid >> 5, lane = tid & 31;

    const float4* W1v = (const float4*)W1;
    #pragma unroll
    for (int t = 0; t < 8; t++) {
        int gi = tid + t * 256;          // gi = j*32 + f4
        int j = gi >> 5, f4 = gi & 31;
        float4 v = W1v[gi];
        __half h0 = __float2half_rn(v.x), h1 = __float2half_rn(v.y);
        __half h2 = __float2half_rn(v.z), h3 = __float2half_rn(v.w);
        uint32_t off = sw_off(j, f4 >> 1) + (uint32_t)(f4 & 1) * 8u;
        *(uint2*)(bsm + off) = pack4(h0, h1, h2, h3);
    }
    for (int idx = tid; idx < H1 * H2; idx += 256) {
        int m = idx >> 6, j = idx & 63;
        gW2t[j * H2 + m] = W2[idx];
    }
    __syncthreads();

    const uint32_t sb = smem_u32(bsm);
    const int kc = wid;                  // warp w -> k-chunk w
    #pragma unroll
    for (int tp = 0; tp < 4; tp++) {
        int row = 16 * tp + ((lane >> 4) << 3) + (lane & 7);
        int chunk = kc * 2 + ((lane >> 3) & 1);
        uint32_t rh[4];
        ldsm_x4(rh, sb + sw_off(row, chunk));
        gBhi[(kc * 4 + tp) * 32 + lane] = make_uint4(rh[0], rh[1], rh[2], rh[3]);
    }
}

__global__ __launch_bounds__(THREADS, 4) void gcn_mma_kernel(
    const float* __restrict__ x,  const float* __restrict__ nb,
    const float* __restrict__ Wc, float* __restrict__ out, int n)
{
    extern __shared__ char sm[];
    const uint32_t sb = smem_u32(sm);
    const int tid = threadIdx.x, wid = tid >> 5, lane = tid & 31;
    const long gbase = (long)blockIdx.x * NPB;

    // ---- Wc^T [m][c] into smem ----
    for (int i2 = tid; i2 < H2 * NC; i2 += THREADS) {
        int c = i2 >> 5, m = i2 & 31;
        ((float*)(sm + SM_WCT))[m * NC + c] = Wc[i2];
    }

    // ---- A rows: warp w owns rows w + 8t (t<15), 3 batches of 5 (MLP=5) ----
    #pragma unroll 1
    for (int b0 = 0; b0 < 15; b0 += 5) {
        float4 q[5];
        #pragma unroll
        for (int t = 0; t < 5; t++) {
            int r = wid + (b0 + t) * 8;
            q[t] = make_float4(0.f, 0.f, 0.f, 0.f);
            if (r < RV) {
                int node = r / 17, sub = r - node * 17;
                long gnode = gbase + node;
                if (gnode < n) {
                    const float4* src = (sub == 0)
                        ? (const float4*)(x + gnode * (long)F)
                        : (const float4*)(nb + (gnode * 16 + (sub - 1)) * (long)F);
                    q[t] = src[lane];
                }
            }
        }
        #pragma unroll
        for (int t = 0; t < 5; t++) {
            int r = wid + (b0 + t) * 8;
            if (r < RV) {
                float4 v = q[t];
                float ss = v.x * v.x + v.y * v.y + v.z * v.z + v.w * v.w;
                #pragma unroll
                for (int o = 16; o > 0; o >>= 1) ss += __shfl_xor_sync(0xffffffffu, ss, o);
                float inv = 1.f / fmaxf(sqrtf(ss), 1e-12f);
                __half h0 = __float2half_rn(v.x * inv);
                __half h1 = __float2half_rn(v.y * inv);
                __half h2 = __float2half_rn(v.z * inv);
                __half h3 = __float2half_rn(v.w * inv);
                uint32_t off = sw_off(r, lane >> 1) + (uint32_t)(lane & 1) * 8u;
                *(uint2*)(sm + SM_AHI + off) = pack4(h0, h1, h2, h3);
            }
        }
    }

    // ---- zero padding rows 119..127 ----
    if (tid < 144) {
        int r = RV + tid / 16, ch = tid & 15;
        *(uint4*)(sm + SM_AHI + sw_off(r, ch)) = make_uint4(0, 0, 0, 0);
    }
    __syncthreads();

    // ---- GEMM: warp grid 4(M) x 2(N); warp tile M=32 x N=32 ----
    // D = Ahi*Bhi^T (fp32 accum); B frags from gmem (L2/L1-hot)
    const int wm = wid >> 1, wn = wid & 1;
    float acc[2][4][4];
    #pragma unroll
    for (int m = 0; m < 2; m++)
        #pragma unroll
        for (int ntl = 0; ntl < 4; ntl++)
            acc[m][ntl][0] = acc[m][ntl][1] = acc[m][ntl][2] = acc[m][ntl][3] = 0.f;

    {
        const int arow = 32 * wm + (lane & 15);
        const int asel = lane >> 4;
        const int tpb = 2 * wn;
        const uint4* pBhi = gBhi + tpb * 32 + lane;

        #pragma unroll
        for (int kc = 0; kc < 8; kc++) {
            uint4 bh0 = pBhi[kc * 128];
            uint4 bh1 = pBhi[kc * 128 + 32];

            uint32_t ahi[2][4];
            #pragma unroll
            for (int m = 0; m < 2; m++)
                ldsm_x4(ahi[m], sb + SM_AHI + sw_off(arow + 16 * m, kc * 2 + asel));

            #pragma unroll
            for (int m = 0; m < 2; m++) {
                mma16816(acc[m][0], ahi[m], bh0.x, bh0.y);
                mma16816(acc[m][1], ahi[m], bh0.z, bh0.w);
                mma16816(acc[m][2], ahi[m], bh1.x, bh1.y);
                mma16816(acc[m][3], ahi[m], bh1.z, bh1.w);
            }
        }
    }
    __syncthreads();   // A tile dead; Hbuf overlays it

    // ---- write C frags to Hbuf[128][65] ----
    float* hb = (float*)(sm + SM_HB);
    #pragma unroll
    for (int m = 0; m < 2; m++) {
        int r0 = 32 * wm + 16 * m + (lane >> 2);
        int c0 = 32 * wn + (lane & 3) * 2;
        #pragma unroll
        for (int ntl = 0; ntl < 4; ntl++) {
            int c = c0 + ntl * 8;
            hb[r0 * 65 + c]           = acc[m][ntl][0];
            hb[r0 * 65 + c + 1]       = acc[m][ntl][1];
            hb[(r0 + 8) * 65 + c]     = acc[m][ntl][2];
            hb[(r0 + 8) * 65 + c + 1] = acc[m][ntl][3];
        }
    }
    __syncthreads();

    // ---- per-node epilogue (W2^T streamed from gmem, L2-hot, coalesced) ----
    long gnode = gbase + wid;
    if (wid < NPB && gnode < n) {
        int base = wid * 17;
        float hx0 = hb[base * 65 + lane], hx1 = hb[base * 65 + 32 + lane];
        float r0 = 0.f, r1 = 0.f;
        #pragma unroll
        for (int k = 0; k < 16; k++) {
            const float* hr = hb + (base + 1 + k) * 65;
            r0 += fmaxf(hx0 + hr[lane], 0.f);
            r1 += fmaxf(hx1 + hr[32 + lane], 0.f);
        }
        float* rb = (float*)(sm + SM_RBUF) + wid * 64;
        rb[lane] = r0;
        rb[lane + 32] = r1;
        __syncwarp();
        float y = 0.f;
        #pragma unroll
        for (int j = 0; j < H1; j++) y += rb[j] * gW2t[j * H2 + lane];
        y = fmaxf(y, 0.f);
        float* yb = (float*)(sm + SM_YBUF) + wid * 32;
        yb[lane] = y;
        __syncwarp();
        if (lane < NC) {
            const float* Wct = (const float*)(sm + SM_WCT);
            float o = 0.f;
            #pragma unroll
            for (int m2 = 0; m2 < H2; m2++) o += yb[m2] * Wct[m2 * NC + lane];
            out[gnode * NC + lane] = o;
        }
    }
}

extern "C" void kernel_launch(void* const* d_in, const int* in_sizes, int n_in,
                              void* d_out, int out_size)
{
    const float* x  = (const float*)d_in[0];
    const float* nb = (const float*)d_in[1];
    const float* W1 = (const float*)d_in[2];
    const float* W2 = (const float*)d_in[3];
    const float* Wc = (const float*)d_in[4];
    float* out = (float*)d_out;

    int n = in_sizes[0] / F;
    gcn_init_kernel<<<1, 256>>>(W1, W2);
    cudaFuncSetAttribute(gcn_mma_kernel,
                         cudaFuncAttributeMaxDynamicSharedMemorySize, SM_TOTAL);
    int grid = (n + NPB - 1) / NPB;
    gcn_mma_kernel<<<grid, THREADS, SM_TOTAL>>>(x, nb, Wc, out, n);
}